// round 6
// baseline (speedup 1.0000x reference)
#include <cuda_runtime.h>
#include <cuda.h>
#include <cstdint>

// Problem constants (reference: D=48, K=12, S=4, BS=8)
#define D_   48
#define N_   (D_ * D_)      // 2304
#define K_   12
#define KK_  (K_ * K_)      // 144
#define NW1_ 10
#define NW_  (NW1_ * NW1_)  // 100
#define BS_  8
#define TILE_FLOATS (K_ * K_ * K_)        // 1728
#define TILE_BYTES  (TILE_FLOATS * 4)     // 6912

// View x[b] as 4D grid x4[pr][pc][qr][qc], each dim 48:
//   x[b, r, c] with r = pr*48+pc, c = qr*48+qc.
// out[b, w, (ia,ib), (ja,jb)] = x4[b][4wr+ia][4wc+ib][4wr+ja][4wc+jb].
// For fixed (b,w,ia): the TMA box [qc=12, qr=12, pc=12, pr=1, b=1] at coords
// (4wc, 4wr, 4wc, 4wr+ia, b) lands densely in smem as [pc=ib][qr=ja][qc=jb]
// = EXACTLY the contiguous 6912B output chunk for (b,w,ia).
// So: one 5D TMA gather -> smem -> one bulk store. No per-element work.

__global__ void __launch_bounds__(32) subm_tma_kernel(
    const __grid_constant__ CUtensorMap tmap, float* __restrict__ out)
{
    __shared__ alignas(128) float tile[TILE_FLOATS];
    __shared__ alignas(8) unsigned long long mbar;

    if (threadIdx.x != 0) return;

    int blk  = blockIdx.x;            // = (b*100 + w)*12 + ia
    int ia   = blk % K_;
    int rest = blk / K_;
    int w    = rest % NW_;
    int b    = rest / NW_;
    int wr = w / NW1_;
    int wc = w % NW1_;

    uint32_t s_tile, s_mbar;
    asm("{ .reg .u64 t; cvta.to.shared.u64 t, %1; cvt.u32.u64 %0, t; }"
        : "=r"(s_tile) : "l"(tile));
    asm("{ .reg .u64 t; cvta.to.shared.u64 t, %1; cvt.u32.u64 %0, t; }"
        : "=r"(s_mbar) : "l"(&mbar));

    asm volatile("mbarrier.init.shared.b64 [%0], 1;" :: "r"(s_mbar) : "memory");
    asm volatile("fence.proxy.async.shared::cta;" ::: "memory");
    asm volatile("mbarrier.arrive.expect_tx.shared.b64 _, [%0], %1;"
                 :: "r"(s_mbar), "r"((uint32_t)TILE_BYTES) : "memory");

    asm volatile(
        "cp.async.bulk.tensor.5d.shared::cta.global.tile.mbarrier::complete_tx::bytes "
        "[%0], [%1, {%2, %3, %4, %5, %6}], [%7];"
        :: "r"(s_tile), "l"(&tmap),
           "r"(4 * wc), "r"(4 * wr), "r"(4 * wc), "r"(4 * wr + ia), "r"(b),
           "r"(s_mbar)
        : "memory");

    // Wait for TMA completion (phase 0)
    asm volatile(
        "{\n\t"
        ".reg .pred P1;\n\t"
        "LW%=:\n\t"
        "mbarrier.try_wait.parity.shared.b64 P1, [%0], 0;\n\t"
        "@P1 bra LD%=;\n\t"
        "bra LW%=;\n\t"
        "LD%=:\n\t"
        "}"
        :: "r"(s_mbar) : "memory");

    // Bulk store the packed tile to its contiguous output slot
    float* dst = out + (size_t)blk * TILE_FLOATS;
    asm volatile(
        "cp.async.bulk.global.shared::cta.bulk_group [%0], [%1], %2;"
        :: "l"(dst), "r"(s_tile), "r"((uint32_t)TILE_BYTES) : "memory");
    asm volatile("cp.async.bulk.commit_group;" ::: "memory");
    asm volatile("cp.async.bulk.wait_group 0;" ::: "memory");
}

// ---------------- fallback (plain gather) in case tensormap encode fails ----
__global__ void __launch_bounds__(256) submanifold_gather_q12(
    const float* __restrict__ x, float* __restrict__ out)
{
    int t = blockIdx.x * 256 + threadIdx.x;
    int q    = t % 36;
    int rest = t / 36;
    int ia   = rest % K_;
    rest     = rest / K_;
    int w    = rest % NW_;
    int b    = rest / NW_;
    int wr = w / NW1_;
    int wc = w % NW1_;
    int ja  = q / 3;
    int sub = q % 3;
    int r0 = (wr * 4 + ia) * D_ + wc * 4;
    int c  = (wr * 4 + ja) * D_ + wc * 4 + sub * 4;
    const float4* src = reinterpret_cast<const float4*>(x + ((size_t)b * N_ + r0) * N_ + c);
    size_t dbase = (((size_t)(b * NW_ + w)) * KK_ + ia * K_) * 36 + q;
    float4* dst = reinterpret_cast<float4*>(out) + dbase;
#pragma unroll
    for (int ib = 0; ib < K_; ib++)
        dst[(size_t)ib * 36] = src[(size_t)ib * (N_ / 4)];
}

// ---------------------------------------------------------------------------

typedef CUresult (*PFN_tmapEncode)(
    CUtensorMap*, CUtensorMapDataType, cuuint32_t, void*,
    const cuuint64_t*, const cuuint64_t*, const cuuint32_t*, const cuuint32_t*,
    CUtensorMapInterleave, CUtensorMapSwizzle, CUtensorMapL2promotion,
    CUtensorMapFloatOOBfill);

extern "C" void kernel_launch(void* const* d_in, const int* in_sizes, int n_in,
                              void* d_out, int out_size)
{
    float* x   = (float*)d_in[0];
    float* out = (float*)d_out;

    PFN_tmapEncode encode = nullptr;
    cudaDriverEntryPointQueryResult qres;
    cudaGetDriverEntryPoint("cuTensorMapEncodeTiled", (void**)&encode,
                            cudaEnableDefault, &qres);

    bool tma_ok = false;
    CUtensorMap tmap;
    if (encode && qres == cudaDriverEntryPointSuccess) {
        // 5D view of x: dims (innermost->outermost) [qc, qr, pc, pr, b]
        cuuint64_t dims[5]    = {48, 48, 48, 48, (cuuint64_t)BS_};
        cuuint64_t strides[4] = {
            48ull * 4,                    // qr: 192 B
            (cuuint64_t)N_ * 4,           // pc: 9216 B
            48ull * N_ * 4,               // pr: 442368 B
            (cuuint64_t)N_ * N_ * 4       // b : 21233664 B
        };
        cuuint32_t box[5]  = {12, 12, 12, 1, 1};
        cuuint32_t estr[5] = {1, 1, 1, 1, 1};
        CUresult r = encode(&tmap, CU_TENSOR_MAP_DATA_TYPE_FLOAT32, 5, (void*)x,
                            dims, strides, box, estr,
                            CU_TENSOR_MAP_INTERLEAVE_NONE,
                            CU_TENSOR_MAP_SWIZZLE_NONE,
                            CU_TENSOR_MAP_L2_PROMOTION_L2_128B,
                            CU_TENSOR_MAP_FLOAT_OOB_FILL_NONE);
        tma_ok = (r == CUDA_SUCCESS);
    }

    if (tma_ok) {
        const int blocks = BS_ * NW_ * K_;   // 9600 tiles
        subm_tma_kernel<<<blocks, 32>>>(tmap, out);
    } else {
        const int total_threads = BS_ * NW_ * K_ * 36;
        submanifold_gather_q12<<<total_threads / 256, 256>>>(x, out);
    }
}

// round 7
// speedup vs baseline: 1.2195x; 1.2195x over previous
#include <cuda_runtime.h>
#include <cstdint>

// Problem constants (reference: D=48, K=12, S=4, BS=8)
#define D_   48
#define N_   (D_ * D_)      // 2304
#define K_   12
#define KK_  (K_ * K_)      // 144
#define NW1_ 10
#define NW_  (NW1_ * NW1_)  // 100
#define BS_  8

// Block = (b, wr, ia, jB) where jB selects 4 of the 12 ja values.
// Source needed by this block = DENSE submatrix of x[b]:
//   rows  r0..r0+47,  r0 = (4*wr+ia)*48      (pc = 0..47 full)
//   cols  c0..c0+191, c0 = (4*wr + 4*jB)*48  (4 full 48-float ja-groups)
// Stage in smem (padded), then write output:
//   out[b, wr*10+wc, ia*12+ib, (4jB+jaLoc)*12+jb]
//     = T[4wc+ib][jaLoc*48 + 4wc + jb]
//
// Loads: fully coalesced 128-bit, zero waste. Stores: contiguous 48-float
// runs per (wc,ib). The strided-gather cost lives entirely in smem.

#define TROWS 48
#define TCOLS 192              // floats per row (dense)
#define TPAD  196              // padded row stride in floats (16B-aligned)
#define LOAD_QUADS (TROWS * (TCOLS / 4))   // 2304
#define OUT_QUADS  (NW1_ * K_ * 12)        // 1440 (wc * ib * 12 quads)

__global__ void __launch_bounds__(256) subm_smem_kernel(
    const float* __restrict__ x, float* __restrict__ out)
{
    __shared__ float T[TROWS * TPAD];   // 37,632 B

    int bi  = blockIdx.x;
    int jB  = bi % 3;
    int ia  = (bi / 3) % K_;
    int wr  = (bi / 36) % NW1_;
    int b   = bi / 360;

    int r0 = (4 * wr + ia) * D_;
    int c0 = (4 * wr + 4 * jB) * D_;

    const float* __restrict__ src = x + ((size_t)b * N_ + r0) * N_ + c0;

    // ---- Phase 1: dense coalesced load into smem (9 iters/thread) ----
#pragma unroll
    for (int it = 0; it < LOAD_QUADS / 256; it++) {
        int k   = threadIdx.x + it * 256;   // quad id
        int row = k / (TCOLS / 4);
        int cq  = k % (TCOLS / 4);
        float4 v = *reinterpret_cast<const float4*>(src + (size_t)row * N_ + cq * 4);
        *reinterpret_cast<float4*>(&T[row * TPAD + cq * 4]) = v;
    }
    __syncthreads();

    // ---- Phase 2: emit output from smem ----
    // q_lin -> (wc, ib, qj): qj = quad within the 48-float j-run
    size_t outbase = (((size_t)b * NW_ + wr * NW1_) * KK_) * KK_;  // + w,i,j terms below
#pragma unroll
    for (int it = 0; it < 6; it++) {
        int q = threadIdx.x + it * 256;
        if (q < OUT_QUADS) {
            int qj = q % 12;
            int ib = (q / 12) % K_;
            int wc = q / 144;

            int jaLoc = qj / 3;
            int sub   = qj % 3;

            int srow = 4 * wc + ib;
            int scol = jaLoc * D_ + 4 * wc + sub * 4;
            float4 v = *reinterpret_cast<const float4*>(&T[srow * TPAD + scol]);

            size_t off = outbase
                       + ((size_t)wc * KK_ + ia * K_ + ib) * KK_
                       + jB * 48 + qj * 4;
            __stcs(reinterpret_cast<float4*>(out + off), v);
        }
    }
}

extern "C" void kernel_launch(void* const* d_in, const int* in_sizes, int n_in,
                              void* d_out, int out_size)
{
    const float* x = (const float*)d_in[0];
    float* out = (float*)d_out;

    const int blocks = BS_ * NW1_ * K_ * 3;   // 2880
    subm_smem_kernel<<<blocks, 256>>>(x, out);
}

// round 8
// speedup vs baseline: 1.6125x; 1.3222x over previous
#include <cuda_runtime.h>
#include <cuda.h>
#include <cstdint>

// Problem constants (reference: D=48, K=12, S=4, BS=8)
#define D_   48
#define N_   (D_ * D_)      // 2304
#define K_   12
#define KK_  (K_ * K_)      // 144
#define NW1_ 10
#define NW_  (NW1_ * NW1_)  // 100
#define BS_  8

// Block = (b, wr, ia, jB), jB in 0..2 selects 4 of the 12 ja values.
// Read set = DENSE 48 x 192-float submatrix of x[b]:
//   rows r0..r0+47,  r0 = (4wr+ia)*48
//   cols c0..c0+191, c0 = (4wr+4jB)*48        (768B-contiguous rows)
// One TMA 3D load stages it in smem (T[row][0..191], unpadded),
// then threads emit output quads straight from smem:
//   out[b, wr*10+wc, ia*12+ib, 48jB + 12jaLoc + 4sub + 0..3]
//     = T[4wc+ib][jaLoc*48 + 4wc + sub*4 .. +3]
// TMA replaces all LDGs -> no L1-MSHR in-flight ceiling on the read side.

#define TROWS 48
#define TCOLS 192
#define TILE_BYTES (TROWS * TCOLS * 4)   // 36864

__global__ void __launch_bounds__(288) subm_tma_smem_kernel(
    const __grid_constant__ CUtensorMap tmap, float* __restrict__ out)
{
    __shared__ alignas(128) float T[TROWS * TCOLS];
    __shared__ alignas(8) unsigned long long mbar;

    int bi  = blockIdx.x;
    int jB  = bi % 3;
    int ia  = (bi / 3) % K_;
    int wr  = (bi / 36) % NW1_;
    int b   = bi / 360;

    uint32_t s_tile, s_mbar;
    asm("{ .reg .u64 t; cvta.to.shared.u64 t, %1; cvt.u32.u64 %0, t; }"
        : "=r"(s_tile) : "l"(T));
    asm("{ .reg .u64 t; cvta.to.shared.u64 t, %1; cvt.u32.u64 %0, t; }"
        : "=r"(s_mbar) : "l"(&mbar));

    if (threadIdx.x == 0) {
        asm volatile("mbarrier.init.shared.b64 [%0], 1;" :: "r"(s_mbar) : "memory");
        asm volatile("fence.proxy.async.shared::cta;" ::: "memory");
    }
    __syncthreads();

    if (threadIdx.x == 0) {
        asm volatile("mbarrier.arrive.expect_tx.shared.b64 _, [%0], %1;"
                     :: "r"(s_mbar), "r"((uint32_t)TILE_BYTES) : "memory");
        int c0 = (4 * wr + 4 * jB) * D_;      // element coord, inner dim
        int r0 = (4 * wr + ia) * D_;
        asm volatile(
            "cp.async.bulk.tensor.3d.shared::cta.global.tile.mbarrier::complete_tx::bytes "
            "[%0], [%1, {%2, %3, %4}], [%5];"
            :: "r"(s_tile), "l"(&tmap), "r"(c0), "r"(r0), "r"(b), "r"(s_mbar)
            : "memory");
    }

    // All threads wait for TMA completion (phase 0), acquire semantics.
    asm volatile(
        "{\n\t"
        ".reg .pred P1;\n\t"
        "LW%=:\n\t"
        "mbarrier.try_wait.parity.shared.b64 P1, [%0], 0;\n\t"
        "@P1 bra LD%=;\n\t"
        "bra LW%=;\n\t"
        "LD%=:\n\t"
        "}"
        :: "r"(s_mbar) : "memory");

    // Phase 2: 1440 output quads; 288 threads, 5 iterations over wc.
    // Per-thread constants: m = tid%144 -> (qj, ib); wcp = tid/144 in {0,1};
    // wc = 2*it + wcp. All div/mod hoisted; loop uses adds only.
    int tid = threadIdx.x;
    int m    = tid % 144;
    int wcp  = tid / 144;
    int qj   = m % K_;
    int ib   = m / K_;
    int jaLoc = qj / 3;
    int sub   = qj % 3;

    // smem float index: (4wc+ib)*192 + jaLoc*48 + 4wc + 4sub = base + wc*772
    int sidx = ib * TCOLS + jaLoc * 48 + sub * 4 + wcp * 772;

    // out float offset: ((b*100 + wr*10 + wc)*144 + ia*12 + ib)*144 + jB*48 + qj*4
    size_t oidx = ((((size_t)b * NW_ + wr * NW1_) * KK_) + ia * K_ + ib) * KK_
                + jB * 48 + qj * 4 + (size_t)wcp * (KK_ * KK_);

#pragma unroll
    for (int it = 0; it < 5; it++) {
        float4 v = *reinterpret_cast<const float4*>(&T[sidx]);
        __stcs(reinterpret_cast<float4*>(out + oidx), v);
        sidx += 2 * 772;
        oidx += 2 * (size_t)(KK_ * KK_);
    }
}

// ---------------- fallback (plain gather) in case tensormap encode fails ----
__global__ void __launch_bounds__(256) submanifold_gather_q12(
    const float* __restrict__ x, float* __restrict__ out)
{
    int t = blockIdx.x * 256 + threadIdx.x;
    int q    = t % 36;
    int rest = t / 36;
    int ia   = rest % K_;
    rest     = rest / K_;
    int w    = rest % NW_;
    int b    = rest / NW_;
    int wr = w / NW1_;
    int wc = w % NW1_;
    int ja  = q / 3;
    int sub = q % 3;
    int r0 = (wr * 4 + ia) * D_ + wc * 4;
    int c  = (wr * 4 + ja) * D_ + wc * 4 + sub * 4;
    const float4* src = reinterpret_cast<const float4*>(x + ((size_t)b * N_ + r0) * N_ + c);
    size_t dbase = (((size_t)(b * NW_ + w)) * KK_ + ia * K_) * 36 + q;
    float4* dst = reinterpret_cast<float4*>(out) + dbase;
#pragma unroll
    for (int ib = 0; ib < K_; ib++)
        dst[(size_t)ib * 36] = src[(size_t)ib * (N_ / 4)];
}

// ---------------------------------------------------------------------------

typedef CUresult (*PFN_tmapEncode)(
    CUtensorMap*, CUtensorMapDataType, cuuint32_t, void*,
    const cuuint64_t*, const cuuint64_t*, const cuuint32_t*, const cuuint32_t*,
    CUtensorMapInterleave, CUtensorMapSwizzle, CUtensorMapL2promotion,
    CUtensorMapFloatOOBfill);

extern "C" void kernel_launch(void* const* d_in, const int* in_sizes, int n_in,
                              void* d_out, int out_size)
{
    float* x   = (float*)d_in[0];
    float* out = (float*)d_out;

    PFN_tmapEncode encode = nullptr;
    cudaDriverEntryPointQueryResult qres;
    cudaGetDriverEntryPoint("cuTensorMapEncodeTiled", (void**)&encode,
                            cudaEnableDefault, &qres);

    bool tma_ok = false;
    CUtensorMap tmap;
    if (encode && qres == cudaDriverEntryPointSuccess) {
        // 3D view of x: [col (2304 floats, inner), row (2304), b (8)]
        cuuint64_t dims[3]    = {(cuuint64_t)N_, (cuuint64_t)N_, (cuuint64_t)BS_};
        cuuint64_t strides[2] = {
            (cuuint64_t)N_ * 4,            // row stride: 9216 B
            (cuuint64_t)N_ * N_ * 4        // batch stride
        };
        cuuint32_t box[3]  = {TCOLS, TROWS, 1};   // 192 x 48 x 1 (768B rows)
        cuuint32_t estr[3] = {1, 1, 1};
        CUresult r = encode(&tmap, CU_TENSOR_MAP_DATA_TYPE_FLOAT32, 3, (void*)x,
                            dims, strides, box, estr,
                            CU_TENSOR_MAP_INTERLEAVE_NONE,
                            CU_TENSOR_MAP_SWIZZLE_NONE,
                            CU_TENSOR_MAP_L2_PROMOTION_L2_128B,
                            CU_TENSOR_MAP_FLOAT_OOB_FILL_NONE);
        tma_ok = (r == CUDA_SUCCESS);
    }

    if (tma_ok) {
        const int blocks = BS_ * NW1_ * K_ * 3;   // 2880
        subm_tma_smem_kernel<<<blocks, 288>>>(tmap, out);
    } else {
        const int total_threads = BS_ * NW_ * K_ * 36;
        submanifold_gather_q12<<<total_threads / 256, 256>>>(x, out);
    }
}

// round 10
// speedup vs baseline: 1.6459x; 1.0207x over previous
#include <cuda_runtime.h>
#include <cstdint>

// Problem constants (reference: D=48, K=12, S=4, BS=8)
#define D_   48
#define N_   (D_ * D_)      // 2304
#define K_   12
#define KK_  (K_ * K_)      // 144
#define NW1_ 10             // (48-12)/4 + 1
#define NW_  (NW1_ * NW1_)  // 100
#define BS_  8
#define QPR_ 36             // float4 quads per output row (144 floats / 4)

// out[b, w, i=(ia,ib), j=(ja,jb)] = x[b, R0+ib, C0+jb]
//   R0 = (wr*4+ia)*48 + wc*4,  C0 = (wr*4+ja)*48 + wc*4
//
// One thread = one column quad q (ja,sub) for ALL 12 ib rows.
// Reads carry an L2::evict_last cache-hint policy (createpolicy +
// ld.global.nc.L2::cache_hint — the 128-bit-legal form) so the ~3x-reused
// gather source stays resident in L2 against the 66MB streaming write.
// Writes are __stcs (evict-first). q runs fastest across lanes -> each of
// the 12 stores is a fully-coalesced 512B warp store.

__device__ __forceinline__ float4 ldg_el(const float4* p, uint64_t pol) {
    float4 v;
    asm volatile("ld.global.nc.L2::cache_hint.v4.f32 {%0,%1,%2,%3}, [%4], %5;"
                 : "=f"(v.x), "=f"(v.y), "=f"(v.z), "=f"(v.w)
                 : "l"(p), "l"(pol));
    return v;
}

__global__ void __launch_bounds__(256) submanifold_gather_q12el(
    const float* __restrict__ x, float* __restrict__ out)
{
    int t = blockIdx.x * 256 + threadIdx.x;   // grid sized exactly
    int q    = t % QPR_;
    int rest = t / QPR_;
    int ia   = rest % K_;
    rest     = rest / K_;
    int w    = rest % NW_;
    int b    = rest / NW_;

    int wr = w / NW1_;
    int wc = w % NW1_;
    int ja  = q / 3;
    int sub = q % 3;

    int r0 = (wr * 4 + ia) * D_ + wc * 4;             // first of 12 source rows
    int c  = (wr * 4 + ja) * D_ + wc * 4 + sub * 4;   // 16B-aligned column

    const float4* __restrict__ src =
        reinterpret_cast<const float4*>(x + ((size_t)b * N_ + r0) * N_ + c);

    size_t dbase = (((size_t)(b * NW_ + w)) * KK_ + ia * K_) * QPR_ + q;
    float4* __restrict__ dst = reinterpret_cast<float4*>(out) + dbase;

    uint64_t pol;
    asm("createpolicy.fractional.L2::evict_last.b64 %0, 1.0;" : "=l"(pol));

    float4 v[K_];
#pragma unroll
    for (int ib = 0; ib < K_; ib++)
        v[ib] = ldg_el(&src[(size_t)ib * (N_ / 4)], pol);

#pragma unroll
    for (int ib = 0; ib < K_; ib++)
        __stcs(&dst[(size_t)ib * QPR_], v[ib]);
}

extern "C" void kernel_launch(void* const* d_in, const int* in_sizes, int n_in,
                              void* d_out, int out_size)
{
    const float* x = (const float*)d_in[0];
    float* out = (float*)d_out;

    const int total_threads = BS_ * NW_ * K_ * QPR_;   // 345,600
    const int blocks = total_threads / 256;            // 1350 exactly
    submanifold_gather_q12el<<<blocks, 256>>>(x, out);
}